// round 10
// baseline (speedup 1.0000x reference)
#include <cuda_runtime.h>
#include <math.h>
#include <stdint.h>

// IAF, 2 MADE flows, B=4096, D=H=64.
// Identity (verified R1/R4-R9): the reference forward scan is the exact inverse
// of z -> z - shift(z), so density = -0.5*D*log(2pi) - 0.5*sum(lv)
// - 0.5*sum(eps^2); only the inverse pass (8 masked [Bx64]@[64x64] GEMMs) runs.
// R10: SINGLE kernel. B-fragments loaded straight from the W arrays with the
// MADE mask applied as a load predicate (masked-off weights are never loaded);
// biases in registers; 16 warps = 2 tiles x 8 n-blocks; tile-scoped named
// barriers; next-layer fragment prefetch; ping-pong act buffers; full unroll.

#define C_DENS (-58.81206612509905f)
#define AST 68

static __device__ __forceinline__ void mma8(float* d, const float* a, float2 b) {
    asm volatile(
        "mma.sync.aligned.m16n8k8.row.col.f32.tf32.tf32.f32 "
        "{%0,%1,%2,%3}, {%4,%5,%6,%7}, {%8,%9}, {%0,%1,%2,%3};"
        : "+f"(d[0]), "+f"(d[1]), "+f"(d[2]), "+f"(d[3])
        : "r"(__float_as_uint(a[0])), "r"(__float_as_uint(a[1])),
          "r"(__float_as_uint(a[2])), "r"(__float_as_uint(a[3])),
          "r"(__float_as_uint(b.x)), "r"(__float_as_uint(b.y)));
}

static __device__ __forceinline__ void tile_bar(int p) {
    asm volatile("bar.sync %0, 256;" :: "r"(p + 1) : "memory");
}

// Masked B-fragment load straight from gmem weight matrix (row-major [64][64]).
// b0 = mask(k0,n)*W[k0][n], b1 = mask(k1,n)*W[k1][n], k0 = kb*8+tig, k1 = k0+4.
// l (layer type) is compile-time under full unroll -> mask branch folds.
static __device__ __forceinline__ float2 loadWfrag(
    const float* __restrict__ src, int l, int kb, int tig, int n, int nmod)
{
    const int k0 = kb * 8 + tig;          // <= 59, no %63 fix needed
    const int k1 = k0 + 4;                // <= 63
    const int k1m = (k1 == 63) ? 0 : k1;
    bool m0, m1;
    if (l == 0)      { m0 = (k0  <= nmod); m1 = (k1  <= nmod); }   // m_in (raw k)
    else if (l == 3) { m0 = (k0  <  n);    m1 = (k1m <  n);    }   // m_out
    else             { m0 = (k0  <= nmod); m1 = (k1m <= nmod); }   // m_hid (k0%63==k0)
    float2 r;
    r.x = m0 ? __ldg(src + k0 * 64 + n) : 0.0f;
    r.y = m1 ? __ldg(src + k1 * 64 + n) : 0.0f;
    return r;
}

__global__ __launch_bounds__(512, 1)
void iaf_main(const float* __restrict__ zm, const float* __restrict__ lv,
              const float* __restrict__ ep,
              const float* __restrict__ W0, const float* __restrict__ b0,
              const float* __restrict__ W1, const float* __restrict__ b1,
              const float* __restrict__ W2, const float* __restrict__ b2,
              const float* __restrict__ Wo, const float* __restrict__ bo,
              float* __restrict__ out, int B)
{
    __shared__ float act[2][2][16][AST];   // [buf][tile][row][col]
    __shared__ float zbuf[2][16][AST];     // exact-fp32 z
    const int t = threadIdx.x;
    const int lane = t & 31, wid = t >> 5;
    const int p = wid >> 3, h = wid & 7;   // tile, n-block (8 cols)
    const int g = lane >> 2, tig = lane & 3;
    const int rowbase = blockIdx.x * 32 + p * 16;
    const int n    = h * 8 + g;            // this lane's weight column
    const int nmod = (n == 63) ? 0 : n;    // n % 63
    const int c    = 8 * h + 2 * tig;      // this lane's output column pair

    // Weight matrices in execution order li=0..7 (flow 1 then flow 0).
    const float* Wseq[8] = { W0 + 4096, W1 + 4096, W2 + 4096, Wo + 4096,
                             W0,        W1,        W2,        Wo        };
    const int    Lseq[8] = { 0, 1, 2, 3, 0, 1, 2, 3 };

    // Biases for this lane's columns, all 8 layers, into registers.
    float2 biasr[8];
    {
        const float* Bseq[8] = { b0 + 64, b1 + 64, b2 + 64, bo + 64,
                                 b0,      b1,      b2,      bo      };
        #pragma unroll
        for (int i = 0; i < 8; ++i)
            biasr[i] = *(const float2*)(Bseq[i] + c);
    }

    // Prefetch layer-0 B-fragments (overlaps with init below).
    float2 Bcur[8], Bnxt[8];
    #pragma unroll
    for (int kb = 0; kb < 8; ++kb)
        Bcur[kb] = loadWfrag(Wseq[0], 0, kb, tig, n, nmod);

    // ---- Init: z0 = zm + exp(0.5*lv)*eps; density.
    {
        int r = t >> 4, seg = t & 15;      // 32 rows x 16 col-segments
        int pi = r >> 4, ri = r & 15;
        int gr = blockIdx.x * 32 + r;
        bool v = gr < B;
        int col = seg * 4;
        const size_t go = (size_t)gr * 64 + col;
        float4 a = v ? *(const float4*)(zm + go) : make_float4(0,0,0,0);
        float4 b = v ? *(const float4*)(lv + go) : make_float4(0,0,0,0);
        float4 cc = v ? *(const float4*)(ep + go) : make_float4(0,0,0,0);
        float4 z4;
        z4.x = a.x + __expf(0.5f * b.x) * cc.x;
        z4.y = a.y + __expf(0.5f * b.y) * cc.y;
        z4.z = a.z + __expf(0.5f * b.z) * cc.z;
        z4.w = a.w + __expf(0.5f * b.w) * cc.w;
        *(float4*)&act[0][pi][ri][col] = z4;
        *(float4*)&zbuf[pi][ri][col]   = z4;
        float slv = b.x + b.y + b.z + b.w;
        float se2 = cc.x*cc.x + cc.y*cc.y + cc.z*cc.z + cc.w*cc.w;
        #pragma unroll
        for (int m = 1; m <= 8; m <<= 1) {
            slv += __shfl_xor_sync(0xffffffffu, slv, m);
            se2 += __shfl_xor_sync(0xffffffffu, se2, m);
        }
        if (seg == 0 && v)
            out[(size_t)B * 64 + gr] = C_DENS - 0.5f * slv - 0.5f * se2;
    }
    __syncthreads();

    // ---- 8 chained layers, fully unrolled; tile-scoped barriers.
    #pragma unroll
    for (int li = 0; li < 8; ++li) {
        const int l  = Lseq[li];
        const int rd = li & 1, wr = (li + 1) & 1;

        // Prefetch next layer's B-fragments (overlaps this layer's MMAs).
        if (li < 7) {
            #pragma unroll
            for (int kb = 0; kb < 8; ++kb)
                Bnxt[kb] = loadWfrag(Wseq[li + 1], Lseq[li + 1], kb, tig, n, nmod);
        }

        // A-fragments (conflict-free LDS: bank = 4g + tig).
        float Afr[32];
        #pragma unroll
        for (int kb = 0; kb < 8; ++kb) {
            Afr[kb*4+0] = act[rd][p][g][kb*8 + tig];
            Afr[kb*4+1] = act[rd][p][g+8][kb*8 + tig];
            Afr[kb*4+2] = act[rd][p][g][kb*8 + tig + 4];
            Afr[kb*4+3] = act[rd][p][g+8][kb*8 + tig + 4];
        }

        float acc[4];
        #pragma unroll
        for (int i = 0; i < 4; ++i) acc[i] = 0.f;
        #pragma unroll
        for (int kb = 0; kb < 8; ++kb)
            mma8(acc, Afr + kb*4, Bcur[kb]);

        const float2 bias = biasr[li];

        if (l < 3) {
            float v0 = fmaxf(acc[0] + bias.x, 0.f);
            float v1 = fmaxf(acc[1] + bias.y, 0.f);
            float v2 = fmaxf(acc[2] + bias.x, 0.f);
            float v3 = fmaxf(acc[3] + bias.y, 0.f);
            *(float2*)&act[wr][p][g][c]   = make_float2(v0, v1);
            *(float2*)&act[wr][p][g+8][c] = make_float2(v2, v3);
            tile_bar(p);
        } else {
            float2 z0 = *(float2*)&zbuf[p][g][c];
            float2 z1 = *(float2*)&zbuf[p][g+8][c];
            float zn0 = z0.x - (acc[0] + bias.x);
            float zn1 = z0.y - (acc[1] + bias.y);
            float zn2 = z1.x - (acc[2] + bias.x);
            float zn3 = z1.y - (acc[3] + bias.y);
            if (li == 3) {
                tile_bar(p);           // zbuf reads done before reversed writes
                const int rc = 62 - c;
                float2 w0 = make_float2(zn1, zn0);
                float2 w1 = make_float2(zn3, zn2);
                *(float2*)&act[wr][p][g][rc]   = w0;
                *(float2*)&act[wr][p][g+8][rc] = w1;
                *(float2*)&zbuf[p][g][rc]      = w0;
                *(float2*)&zbuf[p][g+8][rc]    = w1;
                tile_bar(p);
            } else {
                const int r0 = rowbase + g, r1 = r0 + 8;
                if (r0 < B)
                    *(float2*)(out + (size_t)r0*64 + c) = make_float2(zn0, zn1);
                if (r1 < B)
                    *(float2*)(out + (size_t)r1*64 + c) = make_float2(zn2, zn3);
            }
        }

        // Rotate prefetch buffer (register renames under full unroll).
        #pragma unroll
        for (int i = 0; i < 8; ++i) Bcur[i] = Bnxt[i];
    }
}

extern "C" void kernel_launch(void* const* d_in, const int* in_sizes, int n_in,
                              void* d_out, int out_size) {
    const float* zm = (const float*)d_in[0];
    const float* lv = (const float*)d_in[1];
    const float* ep = (const float*)d_in[2];
    const float* W0 = (const float*)d_in[3];
    const float* b0 = (const float*)d_in[4];
    const float* W1 = (const float*)d_in[5];
    const float* b1 = (const float*)d_in[6];
    const float* W2 = (const float*)d_in[7];
    const float* b2 = (const float*)d_in[8];
    const float* Wo = (const float*)d_in[9];
    const float* bo = (const float*)d_in[10];

    int B = in_sizes[0] / 64;

    int grid = (B + 31) / 32;
    iaf_main<<<grid, 512>>>(zm, lv, ep, W0, b0, W1, b1, W2, b2, Wo, bo,
                            (float*)d_out, B);
}

// round 11
// speedup vs baseline: 1.0865x; 1.0865x over previous
#include <cuda_runtime.h>
#include <math.h>
#include <stdint.h>

// IAF, 2 MADE flows, B=4096, D=H=64.
// Identity (verified R1/R4-R10): the reference forward scan is the exact
// inverse of z -> z - shift(z), so density = -0.5*D*log(2pi) - 0.5*sum(lv)
// - 0.5*sum(eps^2); only the inverse pass (8 masked [Bx64]@[64x64] GEMMs) runs.
// R11: single kernel. Preamble stages all 8 masked weight matrices into
// row-major padded smem (coalesced LDG + float4 STS). Mainloop = R9:
// 16 warps = 2 tiles x 8 n-blocks, frag LDS, tile-scoped named barriers,
// register biases, ping-pong act buffers, fully unrolled layers.

#define C_DENS (-58.81206612509905f)
#define AST 68                 // padded row stride (floats)
#define WST (64 * AST)         // floats per staged matrix (4352)

static __device__ __forceinline__ void mma8(float* d, const float* a, float2 b) {
    asm volatile(
        "mma.sync.aligned.m16n8k8.row.col.f32.tf32.tf32.f32 "
        "{%0,%1,%2,%3}, {%4,%5,%6,%7}, {%8,%9}, {%0,%1,%2,%3};"
        : "+f"(d[0]), "+f"(d[1]), "+f"(d[2]), "+f"(d[3])
        : "r"(__float_as_uint(a[0])), "r"(__float_as_uint(a[1])),
          "r"(__float_as_uint(a[2])), "r"(__float_as_uint(a[3])),
          "r"(__float_as_uint(b.x)), "r"(__float_as_uint(b.y)));
}

static __device__ __forceinline__ void tile_bar(int p) {
    asm volatile("bar.sync %0, 256;" :: "r"(p + 1) : "memory");
}

__global__ __launch_bounds__(512, 1)
void iaf_main(const float* __restrict__ zm, const float* __restrict__ lv,
              const float* __restrict__ ep,
              const float* __restrict__ W0, const float* __restrict__ b0,
              const float* __restrict__ W1, const float* __restrict__ b1,
              const float* __restrict__ W2, const float* __restrict__ b2,
              const float* __restrict__ Wo, const float* __restrict__ bo,
              float* __restrict__ out, int B)
{
    extern __shared__ float sm[];
    float* wsm  = sm;                         // [8][64][AST] masked weights
    float* actb = wsm + 8 * WST;              // [2][2][16][AST] ping-pong acts
    float* zb   = actb + 2 * 2 * 16 * AST;    // [2][16][AST] exact z

    const int t = threadIdx.x;
    const int lane = t & 31, wid = t >> 5;
    const int p = wid >> 3, h = wid & 7;      // tile, n-block (8 cols)
    const int g = lane >> 2, tig = lane & 3;
    const int rowbase = blockIdx.x * 32 + p * 16;
    const int n = h * 8 + g;                  // this lane's weight column
    const int c = 8 * h + 2 * tig;            // this lane's output column pair

    // ---- Preamble: stage masked weights (coalesced LDG, float4 STS).
    // d_h[h] = h % 63 + 1. Masks: m_in: k <= n%63 ; m_hid: k%63 <= n%63 ;
    // m_out: k%63 < n.  mat = f*4 + l.
    #pragma unroll
    for (int it = 0; it < 16; ++it) {
        int i   = t + it * 512;               // float4 granule, 0..8191
        int mat = i >> 10;
        int f = mat >> 2, l = mat & 3;
        int e  = (i & 1023) << 2;
        int k  = e >> 6, n0 = e & 63;
        const float* src = (l == 0) ? W0 : (l == 1) ? W1 : (l == 2) ? W2 : Wo;
        float4 w = *(const float4*)(src + f * 4096 + k * 64 + n0);
        int km = (k == 63) ? 0 : k;           // k % 63
        float vals[4] = {w.x, w.y, w.z, w.w};
        #pragma unroll
        for (int q = 0; q < 4; ++q) {
            int nn = n0 + q;
            int nm = (nn == 63) ? 0 : nn;
            bool keep = (l == 0) ? (k <= nm)
                      : (l == 3) ? (km < nn)
                                 : (km <= nm);
            if (!keep) vals[q] = 0.0f;
        }
        *(float4*)(wsm + mat * WST + k * AST + n0) =
            make_float4(vals[0], vals[1], vals[2], vals[3]);
    }

    // Biases for this lane's columns, all 8 layers (exec order), registers.
    float2 biasr[8];
    {
        const float* Bseq[8] = { b0 + 64, b1 + 64, b2 + 64, bo + 64,
                                 b0,      b1,      b2,      bo      };
        #pragma unroll
        for (int i = 0; i < 8; ++i)
            biasr[i] = *(const float2*)(Bseq[i] + c);
    }

    // ---- Init: z0 = zm + exp(0.5*lv)*eps; density.
    {
        int r = t >> 4, seg = t & 15;         // 32 rows x 16 col-segments
        int pi = r >> 4, ri = r & 15;
        int gr = blockIdx.x * 32 + r;
        bool v = gr < B;
        int col = seg * 4;
        const size_t go = (size_t)gr * 64 + col;
        float4 a = v ? *(const float4*)(zm + go) : make_float4(0,0,0,0);
        float4 b = v ? *(const float4*)(lv + go) : make_float4(0,0,0,0);
        float4 cc = v ? *(const float4*)(ep + go) : make_float4(0,0,0,0);
        float4 z4;
        z4.x = a.x + __expf(0.5f * b.x) * cc.x;
        z4.y = a.y + __expf(0.5f * b.y) * cc.y;
        z4.z = a.z + __expf(0.5f * b.z) * cc.z;
        z4.w = a.w + __expf(0.5f * b.w) * cc.w;
        *(float4*)(actb + ((0 * 2 + pi) * 16 + ri) * AST + col) = z4;
        *(float4*)(zb   + (pi * 16 + ri) * AST + col)           = z4;
        float slv = b.x + b.y + b.z + b.w;
        float se2 = cc.x*cc.x + cc.y*cc.y + cc.z*cc.z + cc.w*cc.w;
        #pragma unroll
        for (int m = 1; m <= 8; m <<= 1) {
            slv += __shfl_xor_sync(0xffffffffu, slv, m);
            se2 += __shfl_xor_sync(0xffffffffu, se2, m);
        }
        if (seg == 0 && v)
            out[(size_t)B * 64 + gr] = C_DENS - 0.5f * slv - 0.5f * se2;
    }
    __syncthreads();

    const float* zrow0 = zb + (p * 16 + g) * AST;
    const float* zrow1 = zb + (p * 16 + g + 8) * AST;

    // ---- 8 chained layers, fully unrolled; tile-scoped barriers.
    // Execution order mats: flow 1 (4,5,6,7) then flow 0 (0,1,2,3).
    #pragma unroll
    for (int li = 0; li < 8; ++li) {
        const int mat = (li < 4) ? (4 + li) : (li - 4);
        const int l   = mat & 3;
        const int rd  = li & 1, wr = (li + 1) & 1;

        // B-fragments from staged weights (scalar LDS, <=2-way conflicts).
        const float* wb = wsm + mat * WST + n;
        float2 Bf[8];
        #pragma unroll
        for (int kb = 0; kb < 8; ++kb) {
            int k0 = kb * 8 + tig;
            Bf[kb] = make_float2(wb[k0 * AST], wb[(k0 + 4) * AST]);
        }

        // A-fragments (conflict-free LDS: bank = 4g + tig).
        const float* ar0 = actb + ((rd * 2 + p) * 16 + g) * AST;
        const float* ar1 = actb + ((rd * 2 + p) * 16 + g + 8) * AST;
        float Afr[32];
        #pragma unroll
        for (int kb = 0; kb < 8; ++kb) {
            Afr[kb*4+0] = ar0[kb*8 + tig];
            Afr[kb*4+1] = ar1[kb*8 + tig];
            Afr[kb*4+2] = ar0[kb*8 + tig + 4];
            Afr[kb*4+3] = ar1[kb*8 + tig + 4];
        }

        float acc[4];
        #pragma unroll
        for (int i = 0; i < 4; ++i) acc[i] = 0.f;
        #pragma unroll
        for (int kb = 0; kb < 8; ++kb)
            mma8(acc, Afr + kb*4, Bf[kb]);

        const float2 bias = biasr[li];
        float* aw0 = actb + ((wr * 2 + p) * 16 + g) * AST;
        float* aw1 = actb + ((wr * 2 + p) * 16 + g + 8) * AST;

        if (l < 3) {
            float v0 = fmaxf(acc[0] + bias.x, 0.f);
            float v1 = fmaxf(acc[1] + bias.y, 0.f);
            float v2 = fmaxf(acc[2] + bias.x, 0.f);
            float v3 = fmaxf(acc[3] + bias.y, 0.f);
            *(float2*)(aw0 + c) = make_float2(v0, v1);
            *(float2*)(aw1 + c) = make_float2(v2, v3);
            tile_bar(p);
        } else {
            float2 z0 = *(const float2*)(zrow0 + c);
            float2 z1 = *(const float2*)(zrow1 + c);
            float zn0 = z0.x - (acc[0] + bias.x);
            float zn1 = z0.y - (acc[1] + bias.y);
            float zn2 = z1.x - (acc[2] + bias.x);
            float zn3 = z1.y - (acc[3] + bias.y);
            if (li == 3) {
                tile_bar(p);          // zbuf reads done before reversed writes
                const int rc = 62 - c;
                float2 w0 = make_float2(zn1, zn0);
                float2 w1 = make_float2(zn3, zn2);
                *(float2*)(aw0 + rc) = w0;
                *(float2*)(aw1 + rc) = w1;
                *(float2*)((float*)zrow0 + rc) = w0;
                *(float2*)((float*)zrow1 + rc) = w1;
                tile_bar(p);
            } else {
                const int r0 = rowbase + g, r1 = r0 + 8;
                if (r0 < B)
                    *(float2*)(out + (size_t)r0*64 + c) = make_float2(zn0, zn1);
                if (r1 < B)
                    *(float2*)(out + (size_t)r1*64 + c) = make_float2(zn2, zn3);
            }
        }
    }
}

extern "C" void kernel_launch(void* const* d_in, const int* in_sizes, int n_in,
                              void* d_out, int out_size) {
    const float* zm = (const float*)d_in[0];
    const float* lv = (const float*)d_in[1];
    const float* ep = (const float*)d_in[2];
    const float* W0 = (const float*)d_in[3];
    const float* b0 = (const float*)d_in[4];
    const float* W1 = (const float*)d_in[5];
    const float* b1 = (const float*)d_in[6];
    const float* W2 = (const float*)d_in[7];
    const float* b2 = (const float*)d_in[8];
    const float* Wo = (const float*)d_in[9];
    const float* bo = (const float*)d_in[10];

    int B = in_sizes[0] / 64;

    int smem = (8 * WST + 2 * 2 * 16 * AST + 2 * 16 * AST) * (int)sizeof(float);
    cudaFuncSetAttribute(iaf_main, cudaFuncAttributeMaxDynamicSharedMemorySize,
                         smem);
    int grid = (B + 31) / 32;
    iaf_main<<<grid, 512, smem>>>(zm, lv, ep, W0, b0, W1, b1, W2, b2, Wo, bo,
                                  (float*)d_out, B);
}